// round 1
// baseline (speedup 1.0000x reference)
#include <cuda_runtime.h>
#include <math.h>

#define Bx   8
#define Lx   4096
#define Dx   384
#define DIx  768
#define Sx   16
#define DTRx 24
#define Rx   (Bx*Lx)        /* 32768 rows */
#define NCH  32
#define CLEN (Lx/NCH)       /* 128 */

/* ------------- device scratch (static, no allocations) ------------- */
__device__ __align__(128) float g_xn [(size_t)Rx*Dx];
__device__ __align__(128) float g_xz [(size_t)Rx*2*DIx];
__device__ __align__(128) float g_xc [(size_t)Rx*DIx];
__device__ __align__(128) float g_dtr[(size_t)Rx*DTRx];
__device__ __align__(128) float g_Bmat[(size_t)Rx*Sx];
__device__ __align__(128) float g_Cmat[(size_t)Rx*Sx];
__device__ __align__(128) float g_dt [(size_t)Rx*DIx];
__device__ __align__(128) float g_yssm[(size_t)Rx*DIx];
__device__ __align__(128) float g_A  [DIx*Sx];
__device__ __align__(128) float g_hfin[(size_t)Bx*NCH*DIx*Sx];
__device__ __align__(128) float g_Hini[(size_t)Bx*NCH*DIx*Sx];
__device__ __align__(128) float g_dtsum[Bx*NCH*DIx];
__device__ __align__(128) float g_yvpart[Bx*NCH*DIx];
__device__ __align__(128) float g_xpart[Bx*16*Dx];
__device__ __align__(128) float g_pooled[Bx*Dx];
__device__ __align__(128) float g_hfc[Bx*256];

__device__ __forceinline__ float softplusf(float v) {
    return v > 20.f ? v : log1pf(__expf(v));
}
__device__ __forceinline__ float siluf(float v) {
    return v / (1.f + __expf(-v));
}

/* ------------- 1. RMSNorm ------------- */
__global__ __launch_bounds__(128) void rmsnorm_kernel(const float* __restrict__ x,
                                                      const float* __restrict__ w) {
    int row = blockIdx.x, tid = threadIdx.x;
    const float* xr = x + (size_t)row*Dx;
    float v0 = xr[tid], v1 = xr[tid+128], v2 = xr[tid+256];
    float ss = v0*v0 + v1*v1 + v2*v2;
    #pragma unroll
    for (int o = 16; o; o >>= 1) ss += __shfl_xor_sync(0xffffffffu, ss, o);
    __shared__ float sm[4];
    if ((tid & 31) == 0) sm[tid >> 5] = ss;
    __syncthreads();
    float tot = sm[0] + sm[1] + sm[2] + sm[3];
    float sc  = rsqrtf(tot * (1.f/Dx) + 1e-5f);
    float* o = g_xn + (size_t)row*Dx;
    o[tid]     = v0*sc*w[tid];
    o[tid+128] = v1*sc*w[tid+128];
    o[tid+256] = v2*sc*w[tid+256];
}

/* ------------- 2. GEMM1: g_xn[32768,384] @ W_in[384,1536] -> g_xz ------------- */
__global__ __launch_bounds__(256) void gemm_in_kernel(const float* __restrict__ Wb) {
    const int M = Rx, N = 2*DIx, K = Dx;
    __shared__ float As[8][128];
    __shared__ float Bs[8][128];
    int tid = threadIdx.x;
    int bn = blockIdx.x, bm = blockIdx.y;
    const float* Ab = g_xn + (size_t)bm*128*K;
    const float* Bb = Wb + bn*128;
    int arow = tid >> 1, acol = (tid & 1)*4;
    int brow = tid >> 5, bcol = (tid & 31)*4;
    int tx = tid & 15, ty = tid >> 4;
    float acc[8][8] = {};
    for (int k0 = 0; k0 < K; k0 += 8) {
        float4 av = *(const float4*)(Ab + (size_t)arow*K + k0 + acol);
        As[acol+0][arow] = av.x; As[acol+1][arow] = av.y;
        As[acol+2][arow] = av.z; As[acol+3][arow] = av.w;
        *(float4*)(&Bs[brow][bcol]) = *(const float4*)(Bb + (size_t)(k0+brow)*N + bcol);
        __syncthreads();
        #pragma unroll
        for (int k = 0; k < 8; k++) {
            float ra[8], rb[8];
            #pragma unroll
            for (int i = 0; i < 8; i++) ra[i] = As[k][ty*8+i];
            #pragma unroll
            for (int j = 0; j < 8; j++) rb[j] = Bs[k][tx*8+j];
            #pragma unroll
            for (int i = 0; i < 8; i++)
                #pragma unroll
                for (int j = 0; j < 8; j++) acc[i][j] += ra[i]*rb[j];
        }
        __syncthreads();
    }
    float* Cb = g_xz + (size_t)(bm*128 + ty*8)*N + bn*128 + tx*8;
    #pragma unroll
    for (int i = 0; i < 8; i++)
        #pragma unroll
        for (int j = 0; j < 8; j += 4)
            *(float4*)(Cb + (size_t)i*N + j) =
                make_float4(acc[i][j], acc[i][j+1], acc[i][j+2], acc[i][j+3]);
}

/* ------------- 3. causal depthwise conv (K=4) + SiLU ------------- */
__global__ __launch_bounds__(256) void conv_silu_kernel(const float* __restrict__ cw,
                                                        const float* __restrict__ cb) {
    int idx = blockIdx.x*256 + threadIdx.x;   /* over Rx*DIx */
    int d = idx % DIx;
    int row = idx / DIx;
    int t = row & (Lx-1);
    float w0 = cw[d*4+0], w1 = cw[d*4+1], w2 = cw[d*4+2], w3 = cw[d*4+3];
    float acc = cb[d];
    const float* xp = g_xz + (size_t)row*(2*DIx) + d;
    if (t >= 3) acc += w0 * xp[-(size_t)3*(2*DIx)];
    if (t >= 2) acc += w1 * xp[-(size_t)2*(2*DIx)];
    if (t >= 1) acc += w2 * xp[-(size_t)1*(2*DIx)];
    acc += w3 * xp[0];
    g_xc[(size_t)row*DIx + d] = siluf(acc);
}

/* ------------- 4. xproj: g_xc[32768,768] @ W_xproj[768,56] -> dtr/B/C ------------- */
__global__ __launch_bounds__(256) void xproj_kernel(const float* __restrict__ W) {
    __shared__ float As[32][128];
    __shared__ float Ws[32][56];
    int tid = threadIdx.x;
    int m0 = blockIdx.x * 128;
    int rm = (tid >> 3) * 4, cn = (tid & 7) * 7;
    float acc[4][7] = {};
    for (int k0 = 0; k0 < DIx; k0 += 32) {
        #pragma unroll
        for (int l = 0; l < 4; l++) {
            int f = tid + l*256;
            int r = f >> 3, c4 = (f & 7)*4;
            float4 v = *(const float4*)(g_xc + (size_t)(m0+r)*DIx + k0 + c4);
            As[c4+0][r] = v.x; As[c4+1][r] = v.y; As[c4+2][r] = v.z; As[c4+3][r] = v.w;
        }
        #pragma unroll
        for (int l = 0; l < 2; l++) {
            int f = tid + l*256;
            if (f < 448) {
                int kr = f / 14, c4 = (f % 14)*4;
                *(float4*)(&Ws[kr][c4]) = *(const float4*)(W + (size_t)(k0+kr)*56 + c4);
            }
        }
        __syncthreads();
        #pragma unroll
        for (int k = 0; k < 32; k++) {
            float ra[4], rw[7];
            #pragma unroll
            for (int i = 0; i < 4; i++) ra[i] = As[k][rm+i];
            #pragma unroll
            for (int j = 0; j < 7; j++) rw[j] = Ws[k][cn+j];
            #pragma unroll
            for (int i = 0; i < 4; i++)
                #pragma unroll
                for (int j = 0; j < 7; j++) acc[i][j] += ra[i]*rw[j];
        }
        __syncthreads();
    }
    #pragma unroll
    for (int i = 0; i < 4; i++)
        #pragma unroll
        for (int j = 0; j < 7; j++) {
            int cc = cn + j;
            size_t row = (size_t)(m0 + rm + i);
            float v = acc[i][j];
            if (cc < 24)       g_dtr[row*DTRx + cc] = v;
            else if (cc < 40)  g_Bmat[row*Sx + (cc-24)] = v;
            else               g_Cmat[row*Sx + (cc-40)] = v;
        }
}

/* ------------- 5. dt GEMM: g_dtr[32768,24] @ W_dt[24,768] + bias -> softplus ------------- */
__global__ __launch_bounds__(256) void dt_gemm_kernel(const float* __restrict__ Wdt,
                                                      const float* __restrict__ bias) {
    __shared__ float As[64][24];
    __shared__ float Ws[24][128];
    int tid = threadIdx.x;
    int n0 = blockIdx.x * 128, m0 = blockIdx.y * 64;
    #pragma unroll
    for (int l = 0; l < 2; l++) {
        int f = tid + l*256;
        if (f < 384) {
            int r = f / 6, c4 = (f % 6)*4;
            *(float4*)(&As[r][c4]) = *(const float4*)(g_dtr + (size_t)(m0+r)*DTRx + c4);
        }
    }
    #pragma unroll
    for (int l = 0; l < 3; l++) {
        int f = tid + l*256;
        int kr = f >> 5, c4 = (f & 31)*4;
        *(float4*)(&Ws[kr][c4]) = *(const float4*)(Wdt + (size_t)kr*DIx + n0 + c4);
    }
    __syncthreads();
    int rm = (tid >> 5)*8, cn = (tid & 31)*4;
    float acc[8][4] = {};
    #pragma unroll
    for (int k = 0; k < 24; k++) {
        float rw0 = Ws[k][cn], rw1 = Ws[k][cn+1], rw2 = Ws[k][cn+2], rw3 = Ws[k][cn+3];
        #pragma unroll
        for (int i = 0; i < 8; i++) {
            float a = As[rm+i][k];
            acc[i][0] += a*rw0; acc[i][1] += a*rw1; acc[i][2] += a*rw2; acc[i][3] += a*rw3;
        }
    }
    float b0 = bias[n0+cn], b1 = bias[n0+cn+1], b2 = bias[n0+cn+2], b3 = bias[n0+cn+3];
    #pragma unroll
    for (int i = 0; i < 8; i++) {
        float4 o;
        o.x = softplusf(acc[i][0] + b0);
        o.y = softplusf(acc[i][1] + b1);
        o.z = softplusf(acc[i][2] + b2);
        o.w = softplusf(acc[i][3] + b3);
        *(float4*)(g_dt + (size_t)(m0+rm+i)*DIx + n0 + cn) = o;
    }
}

/* ------------- 6. A = -exp(A_log) ------------- */
__global__ void prep_A_kernel(const float* __restrict__ A_log) {
    int i = blockIdx.x*256 + threadIdx.x;
    if (i < DIx*Sx) g_A[i] = -__expf(A_log[i]);
}

/* ------------- 7. scan pass1: per-chunk final state + dt-sum ------------- */
__global__ __launch_bounds__(128) void scan_pass1_kernel() {
    int d = blockIdx.x*128 + threadIdx.x;
    int c = blockIdx.y, b = blockIdx.z;
    float a[Sx], h[Sx];
    const float4* Ap = (const float4*)(g_A + d*Sx);
    #pragma unroll
    for (int q = 0; q < 4; q++) {
        float4 v = Ap[q];
        a[q*4+0] = v.x; a[q*4+1] = v.y; a[q*4+2] = v.z; a[q*4+3] = v.w;
    }
    #pragma unroll
    for (int s = 0; s < Sx; s++) h[s] = 0.f;
    float ds = 0.f;
    int row0 = b*Lx + c*CLEN;
    const float* dtp = g_dt + (size_t)row0*DIx + d;
    const float* xp  = g_xc + (size_t)row0*DIx + d;
    const float4* Bp = (const float4*)(g_Bmat + (size_t)row0*Sx);
    #pragma unroll 2
    for (int t = 0; t < CLEN; t++) {
        float dv = dtp[(size_t)t*DIx];
        float xv = xp[(size_t)t*DIx];
        float4 q0 = Bp[t*4+0], q1 = Bp[t*4+1], q2 = Bp[t*4+2], q3 = Bp[t*4+3];
        float Bv[16] = {q0.x,q0.y,q0.z,q0.w,q1.x,q1.y,q1.z,q1.w,
                        q2.x,q2.y,q2.z,q2.w,q3.x,q3.y,q3.z,q3.w};
        float c1 = dv*xv;
        ds += dv;
        #pragma unroll
        for (int s = 0; s < Sx; s++)
            h[s] = __expf(dv*a[s])*h[s] + c1*Bv[s];
    }
    size_t base = (((size_t)b*NCH + c)*DIx + d)*Sx;
    #pragma unroll
    for (int s = 0; s < Sx; s += 4)
        *(float4*)(g_hfin + base + s) = make_float4(h[s], h[s+1], h[s+2], h[s+3]);
    g_dtsum[(b*NCH + c)*DIx + d] = ds;
}

/* ------------- 8. sequential chunk combine ------------- */
__global__ __launch_bounds__(256) void scan_combine_kernel() {
    int gid = blockIdx.x*256 + threadIdx.x;  /* < 8*768*16 */
    int s = gid & 15;
    int d = (gid >> 4) % DIx;
    int b = gid / (DIx*Sx);
    float a = g_A[d*Sx + s];
    float H = 0.f;
    for (int c = 0; c < NCH; c++) {
        size_t idx = (((size_t)b*NCH + c)*DIx + d)*Sx + s;
        g_Hini[idx] = H;
        float ds = g_dtsum[(b*NCH + c)*DIx + d];
        H = __expf(a*ds)*H + g_hfin[idx];
    }
}

/* ------------- 9. scan pass2: full scan per chunk, emit y ------------- */
__global__ __launch_bounds__(128) void scan_pass2_kernel() {
    int d = blockIdx.x*128 + threadIdx.x;
    int c = blockIdx.y, b = blockIdx.z;
    float a[Sx], h[Sx];
    const float4* Ap = (const float4*)(g_A + d*Sx);
    #pragma unroll
    for (int q = 0; q < 4; q++) {
        float4 v = Ap[q];
        a[q*4+0] = v.x; a[q*4+1] = v.y; a[q*4+2] = v.z; a[q*4+3] = v.w;
    }
    size_t hbase = (((size_t)b*NCH + c)*DIx + d)*Sx;
    #pragma unroll
    for (int q = 0; q < 4; q++) {
        float4 v = *(const float4*)(g_Hini + hbase + q*4);
        h[q*4+0] = v.x; h[q*4+1] = v.y; h[q*4+2] = v.z; h[q*4+3] = v.w;
    }
    int row0 = b*Lx + c*CLEN;
    const float* dtp = g_dt + (size_t)row0*DIx + d;
    const float* xp  = g_xc + (size_t)row0*DIx + d;
    const float4* Bp = (const float4*)(g_Bmat + (size_t)row0*Sx);
    const float4* Cp = (const float4*)(g_Cmat + (size_t)row0*Sx);
    float* yp = g_yssm + (size_t)row0*DIx + d;
    #pragma unroll 2
    for (int t = 0; t < CLEN; t++) {
        float dv = dtp[(size_t)t*DIx];
        float xv = xp[(size_t)t*DIx];
        float4 q0 = Bp[t*4+0], q1 = Bp[t*4+1], q2 = Bp[t*4+2], q3 = Bp[t*4+3];
        float Bv[16] = {q0.x,q0.y,q0.z,q0.w,q1.x,q1.y,q1.z,q1.w,
                        q2.x,q2.y,q2.z,q2.w,q3.x,q3.y,q3.z,q3.w};
        float4 r0 = Cp[t*4+0], r1 = Cp[t*4+1], r2 = Cp[t*4+2], r3 = Cp[t*4+3];
        float Cv[16] = {r0.x,r0.y,r0.z,r0.w,r1.x,r1.y,r1.z,r1.w,
                        r2.x,r2.y,r2.z,r2.w,r3.x,r3.y,r3.z,r3.w};
        float c1 = dv*xv;
        float y = 0.f;
        #pragma unroll
        for (int s = 0; s < Sx; s++) {
            h[s] = __expf(dv*a[s])*h[s] + c1*Bv[s];
            y += h[s]*Cv[s];
        }
        yp[(size_t)t*DIx] = y;
    }
}

/* ------------- 10. mean over L of x (partials, deterministic) ------------- */
__global__ __launch_bounds__(384) void meanx_part_kernel(const float* __restrict__ x) {
    int b = blockIdx.x, cz = blockIdx.y, j = threadIdx.x;
    float acc = 0.f;
    for (int i = 0; i < 256; i++)
        acc += x[((size_t)b*Lx + cz*256 + i)*Dx + j];
    g_xpart[(b*16 + cz)*Dx + j] = acc;
}

/* ------------- 11. yv = (y + xc*Dskip)*silu(z) partial sums over L ------------- */
__global__ __launch_bounds__(256) void finalize_part_kernel(const float* __restrict__ Dskip) {
    int b = blockIdx.x, cc = blockIdx.y, tid = threadIdx.x;
    int t0 = cc*CLEN;
    int d0 = tid, d1 = tid+256, d2 = tid+512;
    float k0 = Dskip[d0], k1 = Dskip[d1], k2 = Dskip[d2];
    float a0 = 0.f, a1 = 0.f, a2 = 0.f;
    for (int i = 0; i < CLEN; i++) {
        size_t row = (size_t)b*Lx + t0 + i;
        const float* yr = g_yssm + row*DIx;
        const float* xr = g_xc + row*DIx;
        const float* zr = g_xz + row*(2*DIx) + DIx;
        float z0 = zr[d0], z1 = zr[d1], z2 = zr[d2];
        a0 += (yr[d0] + xr[d0]*k0) * siluf(z0);
        a1 += (yr[d1] + xr[d1]*k1) * siluf(z1);
        a2 += (yr[d2] + xr[d2]*k2) * siluf(z2);
    }
    g_yvpart[(b*NCH + cc)*DIx + d0] = a0;
    g_yvpart[(b*NCH + cc)*DIx + d1] = a1;
    g_yvpart[(b*NCH + cc)*DIx + d2] = a2;
}

/* ------------- 12. pooled = (sum_x + sum_yv @ W_out)/L ------------- */
__global__ __launch_bounds__(256) void pooled_gemm_kernel(const float* __restrict__ Wout) {
    __shared__ float myv[DIx];
    __shared__ float red[8][32];
    int tid = threadIdx.x;
    int b = blockIdx.x, j0 = blockIdx.y*32;
    for (int f = tid; f < DIx; f += 256) {
        float s = 0.f;
        #pragma unroll 4
        for (int cc = 0; cc < NCH; cc++) s += g_yvpart[(b*NCH + cc)*DIx + f];
        myv[f] = s;
    }
    __syncthreads();
    int j = j0 + (tid & 31), seg = tid >> 5;
    float acc = 0.f;
    for (int d = seg*96; d < seg*96 + 96; d++)
        acc += myv[d] * Wout[(size_t)d*Dx + j];
    red[seg][tid & 31] = acc;
    __syncthreads();
    if (seg == 0) {
        float tot = 0.f;
        #pragma unroll
        for (int s = 0; s < 8; s++) tot += red[s][tid];
        float mx = 0.f;
        #pragma unroll
        for (int cz = 0; cz < 16; cz++) mx += g_xpart[(b*16 + cz)*Dx + j];
        g_pooled[b*Dx + j] = (mx + tot) * (1.f/Lx);
    }
}

/* ------------- 13. fc: pooled[8,384] @ W_fc[384,256] + b_fc ------------- */
__global__ __launch_bounds__(256) void fc_kernel(const float* __restrict__ Wfc,
                                                 const float* __restrict__ bfc) {
    __shared__ float ps[Dx];
    int b = blockIdx.x, tid = threadIdx.x;
    for (int f = tid; f < Dx; f += 256) ps[f] = g_pooled[b*Dx + f];
    __syncthreads();
    float acc = bfc[tid];
    for (int jj = 0; jj < Dx; jj++) acc += ps[jj] * Wfc[(size_t)jj*256 + tid];
    g_hfc[b*256 + tid] = acc;
}

/* ------------- 14. head: batchnorm(8) + relu + cls ------------- */
__global__ __launch_bounds__(256) void head_kernel(const float* __restrict__ gamma,
                                                   const float* __restrict__ beta,
                                                   const float* __restrict__ Wcls,
                                                   const float* __restrict__ bcls,
                                                   float* __restrict__ out) {
    __shared__ float hs[Bx*256];
    int tid = threadIdx.x;
    for (int f = tid; f < Bx*256; f += 256) hs[f] = g_hfc[f];
    __syncthreads();
    int c = tid;
    float mu = 0.f;
    #pragma unroll
    for (int b = 0; b < Bx; b++) mu += hs[b*256 + c];
    mu *= 0.125f;
    float var = 0.f;
    #pragma unroll
    for (int b = 0; b < Bx; b++) { float dd = hs[b*256 + c] - mu; var += dd*dd; }
    var *= 0.125f;
    float inv = rsqrtf(var + 1e-5f);
    float ga = gamma[c], be = beta[c];
    #pragma unroll
    for (int b = 0; b < Bx; b++) {
        float v = (hs[b*256 + c] - mu)*inv*ga + be;
        hs[b*256 + c] = fmaxf(v, 0.f);
    }
    __syncthreads();
    for (int t = tid; t < Bx*40; t += 256) {
        int b = t / 40, n = t % 40;
        float acc = bcls[n];
        for (int c2 = 0; c2 < 256; c2++) acc += hs[b*256 + c2] * Wcls[c2*40 + n];
        out[t] = acc;
    }
}

/* ------------- launch ------------- */
extern "C" void kernel_launch(void* const* d_in, const int* in_sizes, int n_in,
                              void* d_out, int out_size) {
    const float* x       = (const float*)d_in[0];
    const float* ln_w    = (const float*)d_in[1];
    const float* W_in    = (const float*)d_in[2];
    const float* conv_w  = (const float*)d_in[3];
    const float* conv_b  = (const float*)d_in[4];
    const float* W_xproj = (const float*)d_in[5];
    const float* W_dt    = (const float*)d_in[6];
    const float* dt_bias = (const float*)d_in[7];
    const float* A_log   = (const float*)d_in[8];
    const float* Dskip   = (const float*)d_in[9];
    const float* W_out   = (const float*)d_in[10];
    const float* W_fc    = (const float*)d_in[11];
    const float* b_fc    = (const float*)d_in[12];
    const float* bn_g    = (const float*)d_in[13];
    const float* bn_b    = (const float*)d_in[14];
    const float* W_cls   = (const float*)d_in[15];
    const float* b_cls   = (const float*)d_in[16];
    float* out = (float*)d_out;

    rmsnorm_kernel<<<Rx, 128>>>(x, ln_w);
    gemm_in_kernel<<<dim3(12, Rx/128), 256>>>(W_in);
    conv_silu_kernel<<<(Rx*DIx)/256, 256>>>(conv_w, conv_b);
    xproj_kernel<<<Rx/128, 256>>>(W_xproj);
    dt_gemm_kernel<<<dim3(6, Rx/64), 256>>>(W_dt, dt_bias);
    prep_A_kernel<<<48, 256>>>(A_log);
    scan_pass1_kernel<<<dim3(6, NCH, Bx), 128>>>();
    scan_combine_kernel<<<(Bx*DIx*Sx)/256, 256>>>();
    scan_pass2_kernel<<<dim3(6, NCH, Bx), 128>>>();
    meanx_part_kernel<<<dim3(Bx, 16), 384>>>(x);
    finalize_part_kernel<<<dim3(Bx, NCH), 256>>>(Dskip);
    pooled_gemm_kernel<<<dim3(Bx, 12), 256>>>(W_out);
    fc_kernel<<<Bx, 256>>>(W_fc, b_fc);
    head_kernel<<<1, 256>>>(bn_g, bn_b, W_cls, b_cls, out);
}